// round 5
// baseline (speedup 1.0000x reference)
#include <cuda_runtime.h>
#include <math.h>

// LSTM: S=512, B=64, I=H=1024, fp32.
//  Phase 1: gates_x[s,b,:] = x[s,b,:] @ W_ih^T + b_ih + b_hh   (one GEMM)
//  Phase 2: 512 sequential steps: gates = gates_x[t] + h @ W_hh^T ; cell update
// Packed fma.rn.f32x2 used everywhere: accumulate (even-k, odd-k) partial sums
// in one 64-bit register, horizontal-add in the epilogue. Bitwise-orderings
// differ from reference only at fp32 rounding level (~1e-7).
//
// Output layout (flatten of (output, (h_last, c_last))):
//   [0, S*B*H)             output (h at every step)
//   [S*B*H, +B*H)          h_last
//   [S*B*H+B*H, +B*H)      c_last

typedef unsigned long long u64;

#define SEQ 512
#define BATCH 64
#define HID 1024
#define G4 4096
#define BH (BATCH * HID)

// scratch (allocation-free rule: __device__ globals)
__device__ float g_gx[(size_t)SEQ * BATCH * G4];   // precomputed input gates
__device__ float g_c[BATCH * HID];                 // running cell state

static __device__ __forceinline__ void ffma2(u64 &d, u64 a, u64 b) {
    asm volatile("fma.rn.f32x2 %0, %1, %2, %0;" : "+l"(d) : "l"(a), "l"(b));
}
static __device__ __forceinline__ u64 pack2(float x, float y) {
    u64 r; asm("mov.b64 %0, {%1, %2};" : "=l"(r) : "f"(x), "f"(y)); return r;
}
static __device__ __forceinline__ float hadd2(u64 v) {
    float x, y; asm("mov.b64 {%0, %1}, %2;" : "=f"(x), "=f"(y) : "l"(v));
    return x + y;
}

// ---------------------------------------------------------------------------
// Phase 1 GEMM: C[m][n] = sum_k X[m][k] * Wih[n][k] + (bih[n] + bhh[n])
// M=32768, N=4096, K=1024. BM=BN=128, BK=16, 512 threads, 8m x 4n per thread.
// SMEM layout: u64 [kpair][row] (kpair = k/2), row padded to 129 u64.
//   A compute loads: whole warp same address (tm = warpid) -> broadcast.
//   B compute loads: lane-consecutive n -> conflict-free.
// ---------------------------------------------------------------------------
__global__ __launch_bounds__(512, 1)
void gemm_gates_x(const float* __restrict__ X, const float* __restrict__ W,
                  const float* __restrict__ bih, const float* __restrict__ bhh)
{
    __shared__ u64 As[2][8][129];
    __shared__ u64 Bs[2][8][129];

    const int t  = threadIdx.x;
    const int n0 = blockIdx.x * 128;     // n fastest -> W + shared X rows L2-hot
    const int m0 = blockIdx.y * 128;

    // loader coords: one float4 of A and of B per thread per k-tile
    const int lrow = t >> 2;             // 0..127
    const int lq   = t & 3;              // k-quad 0..3 (covers BK=16)
    const float* ap = X + (size_t)(m0 + lrow) * 1024 + lq * 4;
    const float* bp = W + (size_t)(n0 + lrow) * 1024 + lq * 4;

    // compute coords
    const int tn = t & 31;               // n = n0 + tn + 32*jj
    const int tm = t >> 5;               // m = m0 + tm*8 + i

    u64 acc[8][4];
#pragma unroll
    for (int i = 0; i < 8; i++)
#pragma unroll
        for (int jj = 0; jj < 4; jj++) acc[i][jj] = 0ull;

    float4 av = *(const float4*)ap;
    float4 bv = *(const float4*)bp;
    As[0][lq * 2][lrow]     = pack2(av.x, av.y);
    As[0][lq * 2 + 1][lrow] = pack2(av.z, av.w);
    Bs[0][lq * 2][lrow]     = pack2(bv.x, bv.y);
    Bs[0][lq * 2 + 1][lrow] = pack2(bv.z, bv.w);
    __syncthreads();

    int buf = 0;
    for (int kt = 0; kt < 64; kt++) {
        if (kt < 63) {
            av = *(const float4*)(ap + (kt + 1) * 16);
            bv = *(const float4*)(bp + (kt + 1) * 16);
        }
#pragma unroll
        for (int q = 0; q < 8; q++) {
            u64 a8[8], b4[4];
#pragma unroll
            for (int i = 0; i < 8; i++) a8[i] = As[buf][q][tm * 8 + i];
#pragma unroll
            for (int jj = 0; jj < 4; jj++) b4[jj] = Bs[buf][q][tn + 32 * jj];
#pragma unroll
            for (int i = 0; i < 8; i++)
#pragma unroll
                for (int jj = 0; jj < 4; jj++) ffma2(acc[i][jj], a8[i], b4[jj]);
        }
        if (kt < 63) {
            As[buf ^ 1][lq * 2][lrow]     = pack2(av.x, av.y);
            As[buf ^ 1][lq * 2 + 1][lrow] = pack2(av.z, av.w);
            Bs[buf ^ 1][lq * 2][lrow]     = pack2(bv.x, bv.y);
            Bs[buf ^ 1][lq * 2 + 1][lrow] = pack2(bv.z, bv.w);
            __syncthreads();
            buf ^= 1;
        }
    }

#pragma unroll
    for (int jj = 0; jj < 4; jj++) {
        const int n = n0 + tn + 32 * jj;
        const float bias = bih[n] + bhh[n];
#pragma unroll
        for (int i = 0; i < 8; i++) {
            const int m = m0 + tm * 8 + i;
            g_gx[(size_t)m * G4 + n] = hadd2(acc[i][jj]) + bias;
        }
    }
}

// ---------------------------------------------------------------------------
// Phase 2: one launch per time step.
// Grid: 128 CTAs (each owns 8 j-columns, all 64 batches, all 4 gates).
// Block: 128 threads: j = tid&7, batch-group bg = tid>>3 -> 4 batches/thread.
// Thread accumulates 4 gates x 4 batches in packed f32x2; cell update fuses
// in-register (no cross-thread exchange). h and the CTA's 32 W_hh rows are
// staged through SMEM in 256-float k-chunks (rows padded to 129 u64 ->
// conflict-free LDS.64). W_hh (16MB) stays L2-resident across all 512 steps.
// ---------------------------------------------------------------------------
#define STEP_SMEM ((64 + 32) * 129 * 8)   // 99072 bytes

__global__ __launch_bounds__(128, 1)
void lstm_step(int t, const float* __restrict__ h0, const float* __restrict__ c0,
               const float* __restrict__ Whh, float* __restrict__ out)
{
    extern __shared__ u64 sm[];
    u64 (*hs)[129] = (u64(*)[129])sm;             // [64 b][128 kpair]
    u64 (*ws)[129] = (u64(*)[129])(sm + 64 * 129); // [32 rows][128 kpair]

    const int tid = threadIdx.x;
    const int j   = tid & 7;
    const int bg  = tid >> 3;       // 0..15
    const int b0  = bg * 4;
    const int j0  = blockIdx.x * 8;

    const float* h_in = (t == 0) ? h0 : (out + (size_t)(t - 1) * BH);
    const float* c_in = (t == 0) ? c0 : g_c;

    u64 acc[4][4];                  // [gate][bi]
#pragma unroll
    for (int g = 0; g < 4; g++)
#pragma unroll
        for (int bi = 0; bi < 4; bi++) acc[g][bi] = 0ull;

    for (int ck = 0; ck < 4; ck++) {
        const int kbase = ck * 256;
        // stage h chunk: 64 rows x 256 floats
        for (int idx = tid; idx < 4096; idx += 128) {
            const int r = idx >> 6, c4 = idx & 63;
            float4 v = *(const float4*)(h_in + r * 1024 + kbase + c4 * 4);
            hs[r][c4 * 2]     = pack2(v.x, v.y);
            hs[r][c4 * 2 + 1] = pack2(v.z, v.w);
        }
        // stage W chunk: rows (g*1024 + j0 + jr) for g<4, jr<8
        for (int idx = tid; idx < 2048; idx += 128) {
            const int r = idx >> 6, c4 = idx & 63;
            const int grow = (r >> 3) * 1024 + j0 + (r & 7);
            float4 v = *(const float4*)(Whh + (size_t)grow * 1024 + kbase + c4 * 4);
            ws[r][c4 * 2]     = pack2(v.x, v.y);
            ws[r][c4 * 2 + 1] = pack2(v.z, v.w);
        }
        __syncthreads();

#pragma unroll 4
        for (int kp = 0; kp < 128; kp++) {
            u64 w2[4], h2[4];
#pragma unroll
            for (int g = 0; g < 4; g++) w2[g] = ws[g * 8 + j][kp];
#pragma unroll
            for (int bi = 0; bi < 4; bi++) h2[bi] = hs[b0 + bi][kp];
#pragma unroll
            for (int g = 0; g < 4; g++)
#pragma unroll
                for (int bi = 0; bi < 4; bi++) ffma2(acc[g][bi], w2[g], h2[bi]);
        }
        __syncthreads();
    }

    // fused cell update
    const int col = j0 + j;
#pragma unroll
    for (int bi = 0; bi < 4; bi++) {
        const int b = b0 + bi;
        const float* gxp = g_gx + ((size_t)t * BATCH + b) * G4 + col;
        const float gi = hadd2(acc[0][bi]) + gxp[0];
        const float gf = hadd2(acc[1][bi]) + gxp[1024];
        const float gg = hadd2(acc[2][bi]) + gxp[2048];
        const float go = hadd2(acc[3][bi]) + gxp[3072];

        const float ig = 1.0f / (1.0f + expf(-gi));
        const float fg = 1.0f / (1.0f + expf(-gf));
        const float gt = tanhf(gg);
        const float og = 1.0f / (1.0f + expf(-go));

        const float cprev = c_in[b * HID + col];
        const float cn = fg * cprev + ig * gt;
        const float hn = og * tanhf(cn);

        out[(size_t)t * BH + b * HID + col] = hn;
        g_c[b * HID + col] = cn;
        if (t == SEQ - 1) {
            out[(size_t)SEQ * BH + b * HID + col] = hn;           // h_last
            out[(size_t)SEQ * BH + BH + b * HID + col] = cn;      // c_last
        }
    }
}

extern "C" void kernel_launch(void* const* d_in, const int* in_sizes, int n_in,
                              void* d_out, int out_size)
{
    const float* x    = (const float*)d_in[0];
    const float* h0   = (const float*)d_in[1];
    const float* c0   = (const float*)d_in[2];
    const float* Wih  = (const float*)d_in[3];
    const float* bih  = (const float*)d_in[4];
    const float* Whh  = (const float*)d_in[5];
    const float* bhh  = (const float*)d_in[6];
    float* out = (float*)d_out;

    // Phase 1: input-projection GEMM (n-tile fastest for L2 reuse of X rows)
    gemm_gates_x<<<dim3(32, 256), 512>>>(x, Wih, bih, bhh);

    // Phase 2: 512 sequential step kernels (graph nodes)
    cudaFuncSetAttribute(lstm_step, cudaFuncAttributeMaxDynamicSharedMemorySize,
                         STEP_SMEM);
    for (int t = 0; t < SEQ; t++)
        lstm_step<<<128, 128, STEP_SMEM>>>(t, h0, c0, Whh, out);
}